// round 14
// baseline (speedup 1.0000x reference)
#include <cuda_runtime.h>

#define B      8192
#define NB     2048          // bucket = fi >> 15, fi = rn(r * 2^24) < 2^26
#define GRID   8
#define TPB    1024          // GRID*TPB == B
#define FSCALE 16777216.0f   // 2^24
#define CNT1   (1ULL << 44)  // packed (count=1, sum=fi) increment
#define SUMMASK ((1ULL << 44) - 1)

typedef long long          ll;
typedef unsigned long long ull;

// -------- scratch (device globals; zero at load, restored by each replay) ----
// packed histogram word: bits[0:44) = sum of fi, bits[44:64) = count
__device__ __align__(16) ull g_chist[4][NB];  // class-j hist (g=1..3); scan blocks re-zero
__device__ __align__(16) ull g_uinc[3][NB];   // uncensored-i hist per class y
__device__ ull g_total;                        // fixed-point loss numerator
__device__ ull g_cnt;                          // pair count
__device__ int g_bar1, g_done;

__global__ void __launch_bounds__(TPB) fused_kernel(const float4* __restrict__ hz,
                                                    const void* __restrict__ Yp,
                                                    const void* __restrict__ Cp,
                                                    float* __restrict__ out) {
    __shared__ int s_wc[32];
    __shared__ ll  s_ws[32];
    __shared__ ll  s_red[32];
    __shared__ ll  s_red2[32];
    __shared__ int s_last;

    int tid = threadIdx.x, lane = tid & 31, w = tid >> 5;
    int i = blockIdx.x * TPB + tid;

    // ---- hedge: all independent loads issued up front -----------------------
    float4 h   = hz[i];                        // DRAM
    int    y32 = ((const int*)Yp)[i];          // valid iff int32 (always in-bounds)
    int    c32 = ((const int*)Cp)[i];
    int probe = (tid < 128) ? ((const int*)Yp)[2 * tid + 1] : 0;
    int is32 = __syncthreads_or(probe != 0);   // int64 LE high words of [0,3] are 0

    int y, c;
    if (is32) { y = y32; c = c32; }            // no second memory trip
    else      { y = (int)((const ll*)Yp)[i]; c = (int)((const ll*)Cp)[i]; }

    // ================= Phase A: fixed-point risk, <=2 atomics/thread ========
    float r = (h.x + h.y) + (h.z + h.w);
    int fi = (int)__float2ll_rn(r * FSCALE);   // exact-order quantization, < 2^26
    fi = max(0, min((1 << 26) - 1, fi));
    int b = fi >> 15;                          // 2048 buckets, order-consistent
    ull pk = CNT1 | (ull)fi;

    if (y > 0)           atomicAdd(&g_chist[y][b], pk);  // class 0 never "greater"
    if (c == 0 && y < 3) atomicAdd(&g_uinc[y][b], pk);   // y==3 has no target class

    // ================= barrier: non-scan blocks arrive and EXIT =============
    __syncthreads();
    if (blockIdx.x >= 3) {
        if (tid == 0) { __threadfence(); atomicAdd(&g_bar1, 1); }
        return;                                // 5 blocks done — short tail
    }
    if (tid == 0) {
        __threadfence();                       // release this block's writes
        atomicAdd(&g_bar1, 1);
        while (*(volatile int*)&g_bar1 < GRID) { }
        __threadfence();                       // acquire peers' writes
    }
    __syncthreads();

    // ====== scan blocks 0..2: class g = bid+1, suffix scan + dot ============
    int g = blockIdx.x + 1;
    int base = tid * 2;                        // 2 buckets per thread (2048/1024)

    ulonglong2 a0 = __ldcg((const ulonglong2*)&g_chist[g][base]);
    ull ha[2] = {a0.x, a0.y};

    // combined uncensored-i histogram for y < g (packed adds are carry-safe:
    // total sum <= 8192*2^26 = 2^39 < 2^44, total count <= 8192 < 2^20)
    ull ka[2] = {0, 0};
    #pragma unroll
    for (int yy = 0; yy < 3; yy++) {
        if (yy < g) {
            ulonglong2 b0 = __ldcg((const ulonglong2*)&g_uinc[yy][base]);
            ka[0] += b0.x; ka[1] += b0.y;
        }
    }

    // zero our chist for the next replay (values live in registers);
    // g=3 is the sole remaining reader of uinc[2] — zero it here too
    {
        ulonglong2 zl; zl.x = 0ULL; zl.y = 0ULL;
        *(ulonglong2*)&g_chist[g][base] = zl;
        if (g == 3) *(ulonglong2*)&g_uinc[2][base] = zl;
    }

    // unpack class-g histogram; inclusive prefix within 2-bucket chunk
    int ca[2]; ll sa[2];
    ca[0] = (int)(ha[0] >> 44);  sa[0] = (ll)(ha[0] & SUMMASK);
    ca[1] = (int)(ha[1] >> 44);  sa[1] = (ll)(ha[1] & SUMMASK);
    int cs = ca[0] + ca[1];  ll ss = sa[0] + sa[1];
    int vc = cs; ll vs = ss;
    #pragma unroll
    for (int d = 1; d < 32; d <<= 1) {
        int uc = __shfl_up_sync(0xffffffffu, vc, d);
        ll  us = __shfl_up_sync(0xffffffffu, vs, d);
        if (lane >= d) { vc += uc; vs += us; }
    }
    if (lane == 31) { s_wc[w] = vc; s_ws[w] = vs; }
    __syncthreads();
    if (w == 0) {                               // scan the 32 warp totals
        int wc = s_wc[lane]; ll ws = s_ws[lane];
        #pragma unroll
        for (int d = 1; d < 32; d <<= 1) {
            int uc = __shfl_up_sync(0xffffffffu, wc, d);
            ll  us = __shfl_up_sync(0xffffffffu, ws, d);
            if (lane >= d) { wc += uc; ws += us; }
        }
        s_wc[lane] = wc; s_ws[lane] = ws;
    }
    __syncthreads();
    int totc = s_wc[31]; ll tots = s_ws[31];
    int ec = (vc - cs) + (w ? s_wc[w - 1] : 0);   // exclusive prefix before base
    ll  es = (vs - ss) + (w ? s_ws[w - 1] : 0);

    // cross-bucket dot: sum_b uc(b)*S_ex(b) - us(b)*C_ex(b)   (strict buckets > b)
    ll  contrib = 0;
    ull katot   = 0;
    #pragma unroll
    for (int e = 0; e < 2; e++) {
        ll  inc_s = es + (e ? sa[0] : 0) + sa[e];     // inclusive prefix thru base+e
        int inc_c = ec + (e ? ca[0] : 0) + ca[e];
        ll  S_ex = tots - inc_s;                       // suffix over buckets > base+e
        ll  C_ex = (ll)(totc - inc_c);
        int uc = (int)(ka[e] >> 44);
        ll  us = (ll)(ka[e] & SUMMASK);
        contrib += (ll)uc * S_ex - us * C_ex;
        katot   += ka[e];
    }

    // combined block reduce of (contrib, katot)
    #pragma unroll
    for (int d = 16; d > 0; d >>= 1) {
        contrib += __shfl_down_sync(0xffffffffu, contrib, d);
        katot   += (ull)__shfl_down_sync(0xffffffffu, (ll)katot, d);
    }
    if (lane == 0) { s_red[w] = contrib; s_red2[w] = (ll)katot; }
    __syncthreads();
    if (w == 0) {
        ll v = s_red[lane];
        ll k = s_red2[lane];
        #pragma unroll
        for (int d = 16; d > 0; d >>= 1) {
            v += __shfl_down_sync(0xffffffffu, v, d);
            k += __shfl_down_sync(0xffffffffu, k, d);
        }
        if (lane == 0) {
            ull Ug = ((ull)k) >> 44;                       // U_g = #{unc i, y_i < g}
            atomicAdd(&g_total, (ull)v);
            atomicAdd(&g_cnt, (ull)totc * Ug);             // n_g * U_g
            __threadfence();
            s_last = (atomicAdd(&g_done, 1) == 2) ? 1 : 0; // 3 scan blocks total
        }
    }
    __syncthreads();
    if (!s_last) return;

    // ================= finalize (last scan block only) =======================
    if (tid == 0) {
        ull tot = atomicAdd(&g_total, 0ULL);               // forced L2 reads
        ull cc  = atomicAdd(&g_cnt, 0ULL);
        out[0] = (cc > 0)
               ? (float)((double)(ll)tot / ((double)cc * (double)FSCALE))
               : 0.0f;
        g_total = 0ULL;  g_cnt = 0ULL;  g_done = 0;  g_bar1 = 0;
    }
    // zero uinc[0..1] for the next replay (uinc[2] already zeroed by g=3 block)
    {
        ulonglong2 zl; zl.x = 0ULL; zl.y = 0ULL;
        ull* u = &g_uinc[0][0];                            // first 2*NB packed words
        for (int k2 = tid * 2; k2 < 2 * NB; k2 += TPB * 2)
            *(ulonglong2*)&u[k2] = zl;
    }
}

extern "C" void kernel_launch(void* const* d_in, const int* in_sizes, int n_in,
                              void* d_out, int out_size) {
    const float4* hz = (const float4*)d_in[0];  // hazards [8192,4] f32
    // d_in[1] = S (unused by the loss)
    const void* Y = d_in[2];                    // int64 or int32, detected in-kernel
    const void* C = d_in[3];

    fused_kernel<<<GRID, TPB>>>(hz, Y, C, (float*)d_out);
}

// round 15
// speedup vs baseline: 1.1254x; 1.1254x over previous
#include <cuda_runtime.h>

#define B      8192
#define NB     1024          // bucket = fi >> 16, fi = rn(r * 2^24) < 2^26
#define GRID   16
#define TPB    512           // GRID*TPB == B
#define FSCALE 16777216.0f   // 2^24
#define CNT1   (1ULL << 44)  // packed (count=1, sum=fi) increment
#define SUMMASK ((1ULL << 44) - 1)

typedef long long          ll;
typedef unsigned long long ull;

// -------- scratch (device globals; zero at load, restored by each replay) ----
// packed histogram word: bits[0:44) = sum of fi, bits[44:64) = count
__device__ __align__(16) ull g_chist[4][NB];  // class-j hist (g=1..3); scan blocks re-zero
__device__ __align__(16) ull g_uinc[3][NB];   // uncensored-i hist per class y
__device__ ull g_total;                        // fixed-point loss numerator
__device__ ull g_cnt;                          // pair count
__device__ int g_bar1, g_done;

__global__ void __launch_bounds__(TPB) fused_kernel(const float4* __restrict__ hz,
                                                    const void* __restrict__ Yp,
                                                    const void* __restrict__ Cp,
                                                    float* __restrict__ out) {
    __shared__ int s_wc[16];
    __shared__ ll  s_ws[16];
    __shared__ ll  s_red[16];
    __shared__ ll  s_red2[16];
    __shared__ int s_last;

    int tid = threadIdx.x, lane = tid & 31, w = tid >> 5;
    int i = blockIdx.x * TPB + tid;

    // ---- hedge: all independent loads issued up front -----------------------
    float4 h   = hz[i];                        // DRAM
    int    y32 = ((const int*)Yp)[i];          // valid iff int32 (always in-bounds)
    int    c32 = ((const int*)Cp)[i];
    int probe = (tid < 128) ? ((const int*)Yp)[2 * tid + 1] : 0;
    int is32 = __syncthreads_or(probe != 0);   // int64 LE high words of [0,3] are 0

    int y, c;
    if (is32) { y = y32; c = c32; }            // no second memory trip
    else      { y = (int)((const ll*)Yp)[i]; c = (int)((const ll*)Cp)[i]; }

    // ================= Phase A: fixed-point risk, <=2 atomics/thread ========
    float r = (h.x + h.y) + (h.z + h.w);
    int fi = (int)__float2ll_rn(r * FSCALE);   // exact-order quantization, < 2^26
    fi = max(0, min((1 << 26) - 1, fi));
    int b = fi >> 16;                          // 1024 buckets, order-consistent
    ull pk = CNT1 | (ull)fi;

    if (y > 0)           atomicAdd(&g_chist[y][b], pk);  // class 0 never "greater"
    if (c == 0 && y < 3) atomicAdd(&g_uinc[y][b], pk);   // y==3 has no target class

    // ================= barrier: non-scan blocks arrive and EXIT =============
    __syncthreads();
    if (blockIdx.x >= 3) {
        if (tid == 0) { __threadfence(); atomicAdd(&g_bar1, 1); }
        return;                                // 13 blocks done — short tail
    }
    if (tid == 0) {
        __threadfence();                       // release this block's writes
        atomicAdd(&g_bar1, 1);
        while (*(volatile int*)&g_bar1 < GRID) { }
        __threadfence();                       // acquire peers' writes
    }
    __syncthreads();

    // ====== scan blocks 0..2: class g = bid+1, suffix scan + dot ============
    int g = blockIdx.x + 1;
    int base = tid * 2;                        // 2 buckets per thread (1024/512)

    ulonglong2 a0 = __ldcg((const ulonglong2*)&g_chist[g][base]);
    ull ha[2] = {a0.x, a0.y};

    // combined uncensored-i histogram for y < g (packed adds are carry-safe:
    // total sum <= 8192*2^26 = 2^39 < 2^44, total count <= 8192 < 2^20)
    ull ka[2] = {0, 0};
    #pragma unroll
    for (int yy = 0; yy < 3; yy++) {
        if (yy < g) {
            ulonglong2 b0 = __ldcg((const ulonglong2*)&g_uinc[yy][base]);
            ka[0] += b0.x; ka[1] += b0.y;
        }
    }

    // zero our chist for the next replay (values live in registers);
    // g=3 is the sole remaining reader of uinc[2] — zero it here too
    {
        ulonglong2 zl; zl.x = 0ULL; zl.y = 0ULL;
        *(ulonglong2*)&g_chist[g][base] = zl;
        if (g == 3) *(ulonglong2*)&g_uinc[2][base] = zl;
    }

    // unpack class-g histogram; inclusive prefix within 2-bucket chunk
    int ca[2]; ll sa[2];
    ca[0] = (int)(ha[0] >> 44);  sa[0] = (ll)(ha[0] & SUMMASK);
    ca[1] = (int)(ha[1] >> 44);  sa[1] = (ll)(ha[1] & SUMMASK);
    int cs = ca[0] + ca[1];  ll ss = sa[0] + sa[1];
    int vc = cs; ll vs = ss;
    #pragma unroll
    for (int d = 1; d < 32; d <<= 1) {
        int uc = __shfl_up_sync(0xffffffffu, vc, d);
        ll  us = __shfl_up_sync(0xffffffffu, vs, d);
        if (lane >= d) { vc += uc; vs += us; }
    }
    if (lane == 31) { s_wc[w] = vc; s_ws[w] = vs; }
    __syncthreads();
    if (w == 0 && lane < 16) {                  // scan the 16 warp totals
        int wc = s_wc[lane]; ll ws = s_ws[lane];
        #pragma unroll
        for (int d = 1; d < 16; d <<= 1) {
            int uc = __shfl_up_sync(0x0000ffffu, wc, d);
            ll  us = __shfl_up_sync(0x0000ffffu, ws, d);
            if (lane >= d) { wc += uc; ws += us; }
        }
        s_wc[lane] = wc; s_ws[lane] = ws;
    }
    __syncthreads();
    int totc = s_wc[15]; ll tots = s_ws[15];
    int ec = (vc - cs) + (w ? s_wc[w - 1] : 0);   // exclusive prefix before base
    ll  es = (vs - ss) + (w ? s_ws[w - 1] : 0);

    // cross-bucket dot: sum_b uc(b)*S_ex(b) - us(b)*C_ex(b)   (strict buckets > b)
    ll  contrib = 0;
    ull katot   = 0;
    #pragma unroll
    for (int e = 0; e < 2; e++) {
        ll  inc_s = es + (e ? sa[0] : 0) + sa[e];     // inclusive prefix thru base+e
        int inc_c = ec + (e ? ca[0] : 0) + ca[e];
        ll  S_ex = tots - inc_s;                       // suffix over buckets > base+e
        ll  C_ex = (ll)(totc - inc_c);
        int uc = (int)(ka[e] >> 44);
        ll  us = (ll)(ka[e] & SUMMASK);
        contrib += (ll)uc * S_ex - us * C_ex;
        katot   += ka[e];
    }

    // combined block reduce of (contrib, katot)
    #pragma unroll
    for (int d = 16; d > 0; d >>= 1) {
        contrib += __shfl_down_sync(0xffffffffu, contrib, d);
        katot   += (ull)__shfl_down_sync(0xffffffffu, (ll)katot, d);
    }
    if (lane == 0) { s_red[w] = contrib; s_red2[w] = (ll)katot; }
    __syncthreads();
    if (w == 0) {
        ll v = (lane < 16) ? s_red[lane]  : 0;
        ll k = (lane < 16) ? s_red2[lane] : 0;
        #pragma unroll
        for (int d = 8; d > 0; d >>= 1) {
            v += __shfl_down_sync(0xffffffffu, v, d);
            k += __shfl_down_sync(0xffffffffu, k, d);
        }
        if (lane == 0) {
            ull Ug = ((ull)k) >> 44;                       // U_g = #{unc i, y_i < g}
            atomicAdd(&g_total, (ull)v);
            atomicAdd(&g_cnt, (ull)totc * Ug);             // n_g * U_g
            __threadfence();
            s_last = (atomicAdd(&g_done, 1) == 2) ? 1 : 0; // 3 scan blocks total
        }
    }
    __syncthreads();
    if (!s_last) return;

    // ================= finalize (last scan block only) =======================
    if (tid == 0) {
        ull tot = atomicAdd(&g_total, 0ULL);               // forced L2 reads
        ull cc  = atomicAdd(&g_cnt, 0ULL);
        out[0] = (cc > 0)
               ? (float)((double)(ll)tot / ((double)cc * (double)FSCALE))
               : 0.0f;
        g_total = 0ULL;  g_cnt = 0ULL;  g_done = 0;  g_bar1 = 0;
    }
    // zero uinc[0..1] for the next replay (uinc[2] already zeroed by g=3 block)
    {
        ulonglong2 zl; zl.x = 0ULL; zl.y = 0ULL;
        ull* u = &g_uinc[0][0];                            // first 2*NB packed words
        for (int k2 = tid * 2; k2 < 2 * NB; k2 += TPB * 2)
            *(ulonglong2*)&u[k2] = zl;
    }
}

extern "C" void kernel_launch(void* const* d_in, const int* in_sizes, int n_in,
                              void* d_out, int out_size) {
    const float4* hz = (const float4*)d_in[0];  // hazards [8192,4] f32
    // d_in[1] = S (unused by the loss)
    const void* Y = d_in[2];                    // int64 or int32, detected in-kernel
    const void* C = d_in[3];

    fused_kernel<<<GRID, TPB>>>(hz, Y, C, (float*)d_out);
}

// round 16
// speedup vs baseline: 1.1488x; 1.0208x over previous
#include <cuda_runtime.h>

#define B      8192
#define NB     1024          // bucket = fi >> 16, fi = rn(r * 2^24) < 2^26
#define GRID   16
#define TPB    512           // GRID*TPB == B
#define FSCALE 16777216.0f   // 2^24
#define CNT1   (1ULL << 44)  // packed (count=1, sum=fi) increment
#define SUMMASK ((1ULL << 44) - 1)

typedef long long          ll;
typedef unsigned long long ull;

// -------- scratch (device globals; zero at load, restored by each replay) ----
// packed histogram word: bits[0:44) = sum of fi, bits[44:64) = count
__device__ __align__(16) ull g_chist[4][NB];  // class-j hist (g=1..3); block 0 re-zeros
__device__ __align__(16) ull g_uinc[3][NB];   // uncensored-i hist per class y; block 0 re-zeros
__device__ int g_bar1;                         // reset by block 0 after its spin

__global__ void __launch_bounds__(TPB) fused_kernel(const float4* __restrict__ hz,
                                                    const void* __restrict__ Yp,
                                                    const void* __restrict__ Cp,
                                                    float* __restrict__ out) {
    __shared__ int s_wc[3][16];
    __shared__ ll  s_ws[3][16];
    __shared__ ll  s_ku[3][16];
    __shared__ ll  s_red[16];
    __shared__ ull s_ut[3];

    int tid = threadIdx.x, lane = tid & 31, w = tid >> 5;
    int i = blockIdx.x * TPB + tid;

    // ---- hedge: all independent loads issued up front -----------------------
    float4 h   = hz[i];                        // DRAM
    int    y32 = ((const int*)Yp)[i];          // valid iff int32 (always in-bounds)
    int    c32 = ((const int*)Cp)[i];
    int probe = (tid < 128) ? ((const int*)Yp)[2 * tid + 1] : 0;
    int is32 = __syncthreads_or(probe != 0);   // int64 LE high words of [0,3] are 0

    int y, c;
    if (is32) { y = y32; c = c32; }            // no second memory trip
    else      { y = (int)((const ll*)Yp)[i]; c = (int)((const ll*)Cp)[i]; }

    // ================= Phase A: fixed-point risk, <=2 atomics/thread ========
    float r = (h.x + h.y) + (h.z + h.w);
    int fi = (int)__float2ll_rn(r * FSCALE);   // exact-order quantization, < 2^26
    fi = max(0, min((1 << 26) - 1, fi));
    int b = fi >> 16;                          // 1024 buckets, order-consistent
    ull pk = CNT1 | (ull)fi;

    if (y > 0)           atomicAdd(&g_chist[y][b], pk);  // class 0 never "greater"
    if (c == 0 && y < 3) atomicAdd(&g_uinc[y][b], pk);   // y==3 has no target class

    // ============ barrier: 15 blocks arrive and EXIT; block 0 spins =========
    __syncthreads();
    if (blockIdx.x != 0) {
        if (tid == 0) { __threadfence(); atomicAdd(&g_bar1, 1); }
        return;
    }
    if (tid == 0) {
        __threadfence();                       // release this block's writes
        atomicAdd(&g_bar1, 1);
        while (*(volatile int*)&g_bar1 < GRID) { }
        __threadfence();                       // acquire peers' writes
    }
    __syncthreads();

    // ====== block 0: all 3 class scans + dot + finalize, no global state ====
    int base = tid * 2;                        // 2 buckets per thread (1024/512)
    ulonglong2 hc[3], hu[3];
    #pragma unroll
    for (int g2 = 0; g2 < 3; g2++)
        hc[g2] = __ldcg((const ulonglong2*)&g_chist[g2 + 1][base]);
    #pragma unroll
    for (int yy = 0; yy < 3; yy++)
        hu[yy] = __ldcg((const ulonglong2*)&g_uinc[yy][base]);

    {   // zero everything for the next replay (values live in registers)
        ulonglong2 zl; zl.x = 0ULL; zl.y = 0ULL;
        #pragma unroll
        for (int g2 = 0; g2 < 3; g2++) *(ulonglong2*)&g_chist[g2 + 1][base] = zl;
        #pragma unroll
        for (int yy = 0; yy < 3; yy++) *(ulonglong2*)&g_uinc[yy][base] = zl;
    }

    // per-class unpack + warp scans (3 independent chains, ILP-overlapped)
    int ca0[3], ca1[3]; ll sa0[3], sa1[3];
    int vcs[3], css[3]; ll vss[3], sss[3];
    #pragma unroll
    for (int g2 = 0; g2 < 3; g2++) {
        ca0[g2] = (int)(hc[g2].x >> 44); sa0[g2] = (ll)(hc[g2].x & SUMMASK);
        ca1[g2] = (int)(hc[g2].y >> 44); sa1[g2] = (ll)(hc[g2].y & SUMMASK);
        int cs = ca0[g2] + ca1[g2];  ll ss = sa0[g2] + sa1[g2];
        int vc = cs; ll vs = ss;
        #pragma unroll
        for (int d = 1; d < 32; d <<= 1) {
            int uc = __shfl_up_sync(0xffffffffu, vc, d);
            ll  us = __shfl_up_sync(0xffffffffu, vs, d);
            if (lane >= d) { vc += uc; vs += us; }
        }
        if (lane == 31) { s_wc[g2][w] = vc; s_ws[g2][w] = vs; }
        vcs[g2] = vc; vss[g2] = vs; css[g2] = cs; sss[g2] = ss;
    }
    // packed uinc warp totals (for U_g denominators)
    #pragma unroll
    for (int yy = 0; yy < 3; yy++) {
        ull kt = hu[yy].x + hu[yy].y;
        #pragma unroll
        for (int d = 16; d > 0; d >>= 1)
            kt += (ull)__shfl_down_sync(0xffffffffu, (ll)kt, d);
        if (lane == 0) s_ku[yy][w] = (ll)kt;
    }
    __syncthreads();
    // warps 0..2 each scan one class's 16 warp totals + reduce its uinc totals
    if (w < 3 && lane < 16) {
        int wc = s_wc[w][lane]; ll ws = s_ws[w][lane];
        #pragma unroll
        for (int d = 1; d < 16; d <<= 1) {
            int uc = __shfl_up_sync(0x0000ffffu, wc, d);
            ll  us = __shfl_up_sync(0x0000ffffu, ws, d);
            if (lane >= d) { wc += uc; ws += us; }
        }
        s_wc[w][lane] = wc; s_ws[w][lane] = ws;
        ll k = s_ku[w][lane];
        #pragma unroll
        for (int d = 8; d > 0; d >>= 1)
            k += __shfl_down_sync(0x0000ffffu, k, d);
        if (lane == 0) s_ut[w] = (ull)k;
    }
    __syncthreads();

    // cross-bucket dot per class: sum_b uc(b)*S_ex(b) - us(b)*C_ex(b)
    ll contrib = 0;
    #pragma unroll
    for (int g2 = 0; g2 < 3; g2++) {
        int totc = s_wc[g2][15];  ll tots = s_ws[g2][15];
        int ec = (vcs[g2] - css[g2]) + (w ? s_wc[g2][w - 1] : 0);
        ll  es = (vss[g2] - sss[g2]) + (w ? s_ws[g2][w - 1] : 0);
        ull ka0 = hu[0].x, ka1 = hu[0].y;      // uncensored with y < g (packed)
        if (g2 >= 1) { ka0 += hu[1].x; ka1 += hu[1].y; }
        if (g2 >= 2) { ka0 += hu[2].x; ka1 += hu[2].y; }
        {   // bucket base+0
            ll  S_ex = tots - (es + sa0[g2]);
            ll  C_ex = (ll)(totc - (ec + ca0[g2]));
            contrib += (ll)(int)(ka0 >> 44) * S_ex - (ll)(ka0 & SUMMASK) * C_ex;
        }
        {   // bucket base+1
            ll  S_ex = tots - (es + sa0[g2] + sa1[g2]);
            ll  C_ex = (ll)(totc - (ec + ca0[g2] + ca1[g2]));
            contrib += (ll)(int)(ka1 >> 44) * S_ex - (ll)(ka1 & SUMMASK) * C_ex;
        }
    }

    // in-block reduce of contrib (no global atomics, no done counter)
    #pragma unroll
    for (int d = 16; d > 0; d >>= 1)
        contrib += __shfl_down_sync(0xffffffffu, contrib, d);
    if (lane == 0) s_red[w] = contrib;
    __syncthreads();

    if (tid == 0) {
        ll tot = 0;
        #pragma unroll
        for (int k = 0; k < 16; k++) tot += s_red[k];
        ull Tu0 = s_ut[0] >> 44, Tu1 = s_ut[1] >> 44, Tu2 = s_ut[2] >> 44;
        ull n1 = (ull)s_wc[0][15], n2 = (ull)s_wc[1][15], n3 = (ull)s_wc[2][15];
        ull U1 = Tu0, U2 = Tu0 + Tu1, U3 = U2 + Tu2;  // #{unc i : y_i < g}
        ull cnt = n1 * U1 + n2 * U2 + n3 * U3;
        out[0] = (cnt > 0)
               ? (float)((double)tot / ((double)cnt * (double)FSCALE))
               : 0.0f;
        g_bar1 = 0;                            // all 16 arrivals already counted
    }
}

extern "C" void kernel_launch(void* const* d_in, const int* in_sizes, int n_in,
                              void* d_out, int out_size) {
    const float4* hz = (const float4*)d_in[0];  // hazards [8192,4] f32
    // d_in[1] = S (unused by the loss)
    const void* Y = d_in[2];                    // int64 or int32, detected in-kernel
    const void* C = d_in[3];

    fused_kernel<<<GRID, TPB>>>(hz, Y, C, (float*)d_out);
}

// round 17
// speedup vs baseline: 1.1950x; 1.0402x over previous
#include <cuda_runtime.h>

#define B      8192
#define NB     512           // bucket = fi >> 17, fi = rn(r * 2^24) < 2^26
#define GRID   16
#define TPB    512           // GRID*TPB == B; one bucket per thread in block 0
#define FSCALE 16777216.0f   // 2^24
#define CNT1   (1ULL << 44)  // packed (count=1, sum=fi) increment
#define SUMMASK ((1ULL << 44) - 1)

typedef long long          ll;
typedef unsigned long long ull;

// -------- scratch (device globals; zero at load, restored by each replay) ----
// packed histogram word: bits[0:44) = sum of fi, bits[44:64) = count
__device__ __align__(16) ull g_chist[4][NB];  // class-j hist (g=1..3); block 0 re-zeros
__device__ __align__(16) ull g_uinc[3][NB];   // uncensored-i hist per class y; block 0 re-zeros
__device__ int g_bar1;                         // reset by block 0 after its spin

__global__ void __launch_bounds__(TPB) fused_kernel(const float4* __restrict__ hz,
                                                    const void* __restrict__ Yp,
                                                    const void* __restrict__ Cp,
                                                    float* __restrict__ out) {
    __shared__ int s_wc[3][16];
    __shared__ ll  s_ws[3][16];
    __shared__ ll  s_ku[3][16];
    __shared__ ll  s_red[16];
    __shared__ ull s_ut[3];

    int tid = threadIdx.x, lane = tid & 31, w = tid >> 5;
    int i = blockIdx.x * TPB + tid;

    // ---- hedge: all independent loads issued up front -----------------------
    float4 h   = hz[i];                        // DRAM
    int    y32 = ((const int*)Yp)[i];          // valid iff int32 (always in-bounds)
    int    c32 = ((const int*)Cp)[i];
    // warp-local dtype detection: words 1..63 of Y (in-bounds for both dtypes);
    // int64 LE high words of values in [0,3] are all zero
    int probe = ((const int*)Yp)[2 * lane + 1];
    int is32 = __any_sync(0xffffffffu, probe != 0);   // no block barrier

    int y, c;
    if (is32) { y = y32; c = c32; }            // no second memory trip
    else      { y = (int)((const ll*)Yp)[i]; c = (int)((const ll*)Cp)[i]; }

    // ================= Phase A: fixed-point risk, <=2 atomics/thread ========
    float r = (h.x + h.y) + (h.z + h.w);
    int fi = (int)__float2ll_rn(r * FSCALE);   // exact-order quantization, < 2^26
    fi = max(0, min((1 << 26) - 1, fi));
    int b = fi >> 17;                          // 512 buckets, order-consistent
    ull pk = CNT1 | (ull)fi;

    if (y > 0)           atomicAdd(&g_chist[y][b], pk);  // class 0 never "greater"
    if (c == 0 && y < 3) atomicAdd(&g_uinc[y][b], pk);   // y==3 has no target class

    // ============ barrier: 15 blocks arrive and EXIT; block 0 spins =========
    __syncthreads();
    if (blockIdx.x != 0) {
        if (tid == 0) { __threadfence(); atomicAdd(&g_bar1, 1); }
        return;
    }
    if (tid == 0) {
        __threadfence();                       // release this block's writes
        atomicAdd(&g_bar1, 1);
        while (*(volatile int*)&g_bar1 < GRID) { }
        __threadfence();                       // acquire peers' writes
    }
    __syncthreads();

    // ====== block 0: all 3 class scans + dot + finalize, no global state ====
    // one bucket per thread: tid == bucket index
    ull hc[3], hu[3];
    #pragma unroll
    for (int g2 = 0; g2 < 3; g2++) hc[g2] = __ldcg(&g_chist[g2 + 1][tid]);
    #pragma unroll
    for (int yy = 0; yy < 3; yy++) hu[yy] = __ldcg(&g_uinc[yy][tid]);

    // zero everything for the next replay (values live in registers)
    #pragma unroll
    for (int g2 = 0; g2 < 3; g2++) g_chist[g2 + 1][tid] = 0ULL;
    #pragma unroll
    for (int yy = 0; yy < 3; yy++) g_uinc[yy][tid] = 0ULL;

    // per-class unpack + warp-inclusive scans (3 independent chains, ILP)
    int cav[3]; ll sav[3]; int vcs[3]; ll vss[3];
    #pragma unroll
    for (int g2 = 0; g2 < 3; g2++) {
        int ca = (int)(hc[g2] >> 44);  ll sa = (ll)(hc[g2] & SUMMASK);
        int vc = ca; ll vs = sa;
        #pragma unroll
        for (int d = 1; d < 32; d <<= 1) {
            int uc = __shfl_up_sync(0xffffffffu, vc, d);
            ll  us = __shfl_up_sync(0xffffffffu, vs, d);
            if (lane >= d) { vc += uc; vs += us; }
        }
        if (lane == 31) { s_wc[g2][w] = vc; s_ws[g2][w] = vs; }
        cav[g2] = ca; sav[g2] = sa; vcs[g2] = vc; vss[g2] = vs;
    }
    // packed uinc warp totals (for U_g denominators)
    #pragma unroll
    for (int yy = 0; yy < 3; yy++) {
        ull kt = hu[yy];
        #pragma unroll
        for (int d = 16; d > 0; d >>= 1)
            kt += (ull)__shfl_down_sync(0xffffffffu, (ll)kt, d);
        if (lane == 0) s_ku[yy][w] = (ll)kt;
    }
    __syncthreads();
    // warps 0..2 each scan one class's 16 warp totals + reduce its uinc totals
    if (w < 3 && lane < 16) {
        int wc = s_wc[w][lane]; ll ws = s_ws[w][lane];
        #pragma unroll
        for (int d = 1; d < 16; d <<= 1) {
            int uc = __shfl_up_sync(0x0000ffffu, wc, d);
            ll  us = __shfl_up_sync(0x0000ffffu, ws, d);
            if (lane >= d) { wc += uc; ws += us; }
        }
        s_wc[w][lane] = wc; s_ws[w][lane] = ws;
        ll k = s_ku[w][lane];
        #pragma unroll
        for (int d = 8; d > 0; d >>= 1)
            k += __shfl_down_sync(0x0000ffffu, k, d);
        if (lane == 0) s_ut[w] = (ull)k;
    }
    __syncthreads();

    // cross-bucket dot per class: uc(b)*S_ex(b) - us(b)*C_ex(b), strict b'>b
    ll contrib = 0;
    #pragma unroll
    for (int g2 = 0; g2 < 3; g2++) {
        int totc = s_wc[g2][15];  ll tots = s_ws[g2][15];
        int inc_c = vcs[g2] + (w ? s_wc[g2][w - 1] : 0);   // inclusive prefix thru tid
        ll  inc_s = vss[g2] + (w ? s_ws[g2][w - 1] : 0);
        ll  S_ex = tots - inc_s;
        ll  C_ex = (ll)(totc - inc_c);
        ull ka = hu[0];                        // uncensored with y < g (packed)
        if (g2 >= 1) ka += hu[1];
        if (g2 >= 2) ka += hu[2];
        contrib += (ll)(int)(ka >> 44) * S_ex - (ll)(ka & SUMMASK) * C_ex;
    }

    // in-block reduce of contrib (no global atomics)
    #pragma unroll
    for (int d = 16; d > 0; d >>= 1)
        contrib += __shfl_down_sync(0xffffffffu, contrib, d);
    if (lane == 0) s_red[w] = contrib;
    __syncthreads();

    if (tid == 0) {
        ll tot = 0;
        #pragma unroll
        for (int k = 0; k < 16; k++) tot += s_red[k];
        ull Tu0 = s_ut[0] >> 44, Tu1 = s_ut[1] >> 44, Tu2 = s_ut[2] >> 44;
        ull n1 = (ull)s_wc[0][15], n2 = (ull)s_wc[1][15], n3 = (ull)s_wc[2][15];
        ull U1 = Tu0, U2 = Tu0 + Tu1, U3 = U2 + Tu2;  // #{unc i : y_i < g}
        ull cnt = n1 * U1 + n2 * U2 + n3 * U3;
        out[0] = (cnt > 0)
               ? (float)((double)tot / ((double)cnt * (double)FSCALE))
               : 0.0f;
        g_bar1 = 0;                            // all 16 arrivals already counted
    }
}

extern "C" void kernel_launch(void* const* d_in, const int* in_sizes, int n_in,
                              void* d_out, int out_size) {
    const float4* hz = (const float4*)d_in[0];  // hazards [8192,4] f32
    // d_in[1] = S (unused by the loss)
    const void* Y = d_in[2];                    // int64 or int32, detected in-kernel
    const void* C = d_in[3];

    fused_kernel<<<GRID, TPB>>>(hz, Y, C, (float*)d_out);
}